// round 1
// baseline (speedup 1.0000x reference)
#include <cuda_runtime.h>
#include <math.h>

// Problem constants
#define B_   2
#define T_   2048
#define C_   1024
#define H_   16
#define KD_  64
#define VD_  128
#define VBD_ 2048
#define M_   (B_ * T_)          // 4096
#define EPS_ 1.1920929e-07f     // np.finfo(np.float32).eps

// ---------------------------------------------------------------------------
// Scratch (device globals — no allocations allowed)
// ---------------------------------------------------------------------------
__device__ float g_qk[(size_t)M_ * 2 * C_];   // [4096, 2048]  q | k
__device__ float g_v [(size_t)M_ * VBD_];     // [4096, 2048]
__device__ float g_g [(size_t)M_ * VBD_];     // [4096, 2048]
__device__ float g_y [(size_t)M_ * VBD_];     // [4096, 2048]

// ---------------------------------------------------------------------------
// SGEMM + bias: C[M,N] = A[M,K] @ W[K,N] + bias[N]
// 128x128 block tile, BK=16, 256 threads, 8x8 microtile.
// M % 128 == 0, N % 128 == 0, K % 16 == 0 (true for all our shapes).
// ---------------------------------------------------------------------------
__global__ __launch_bounds__(256) void sgemm_bias_k(
    const float* __restrict__ A, const float* __restrict__ W,
    const float* __restrict__ bias, float* __restrict__ Cout,
    int M, int N, int K)
{
    __shared__ float As[16][132];   // [k][m], padded
    __shared__ float Bs[16][128];   // [k][n]

    const int tid = threadIdx.x;
    const int tx  = tid & 15;
    const int ty  = tid >> 4;
    const int m0  = blockIdx.y * 128;
    const int n0  = blockIdx.x * 128;

    float acc[8][8];
#pragma unroll
    for (int i = 0; i < 8; i++)
#pragma unroll
        for (int j = 0; j < 8; j++) acc[i][j] = 0.f;

    for (int kb = 0; kb < K; kb += 16) {
        // Load A tile (128 x 16) transposed into As[k][m]
#pragma unroll
        for (int i = 0; i < 2; i++) {
            int idx = tid + i * 256;
            int row = idx >> 2;       // 0..127
            int kc4 = idx & 3;        // 0..3
            float4 v = *(const float4*)&A[(size_t)(m0 + row) * K + kb + kc4 * 4];
            As[kc4 * 4 + 0][row] = v.x;
            As[kc4 * 4 + 1][row] = v.y;
            As[kc4 * 4 + 2][row] = v.z;
            As[kc4 * 4 + 3][row] = v.w;
        }
        // Load B tile (16 x 128)
#pragma unroll
        for (int i = 0; i < 2; i++) {
            int idx = tid + i * 256;
            int row = idx >> 5;       // 0..15
            int c4  = idx & 31;       // 0..31
            *(float4*)&Bs[row][c4 * 4] =
                *(const float4*)&W[(size_t)(kb + row) * N + n0 + c4 * 4];
        }
        __syncthreads();

#pragma unroll
        for (int kk = 0; kk < 16; kk++) {
            float a[8], b[8];
            *(float4*)&a[0] = *(const float4*)&As[kk][ty * 8];
            *(float4*)&a[4] = *(const float4*)&As[kk][ty * 8 + 4];
            *(float4*)&b[0] = *(const float4*)&Bs[kk][tx * 8];
            *(float4*)&b[4] = *(const float4*)&Bs[kk][tx * 8 + 4];
#pragma unroll
            for (int i = 0; i < 8; i++)
#pragma unroll
                for (int j = 0; j < 8; j++)
                    acc[i][j] += a[i] * b[j];
        }
        __syncthreads();
    }

#pragma unroll
    for (int i = 0; i < 8; i++) {
        int m = m0 + ty * 8 + i;
#pragma unroll
        for (int j = 0; j < 8; j += 4) {
            int n = n0 + tx * 8 + j;
            float4 o;
            o.x = acc[i][j + 0] + bias[n + 0];
            o.y = acc[i][j + 1] + bias[n + 1];
            o.z = acc[i][j + 2] + bias[n + 2];
            o.w = acc[i][j + 3] + bias[n + 3];
            *(float4*)&Cout[(size_t)m * N + n] = o;
        }
    }
}

// ---------------------------------------------------------------------------
// Retention attention, fused normalization + gate.
// Grid: (T/64, B*H). 256 threads.
// Per CTA: 64 query rows of one (b,h). Single pass over causal s-blocks:
//   raw[t][s] = (q.k) * e1[t-t0]*e2[t0-s]    (decay, closed form)
//   accumulate  accV += raw*v,  rden += |raw|
// Epilogue:  ret = accV / (scale_t * clip(rden/scale_t, 1, 5e4))
//            y   = rmsnorm_VD(ret) * g       -> g_y
// ---------------------------------------------------------------------------
struct AttnSmem {
    float Qs [64][68];    // [row][kd]
    float KsT[64][68];    // [kd][s]   (transposed K tile)
    float Ss [64][65];    // [row][s]
    float Vs [64][128];   // [s][vd]
    float e1s[64];
    float e2s[64];
    float dnm[64];
    float ssq[64][16];
};

__global__ __launch_bounds__(256) void retention_attn(
    const float* __restrict__ qk, const float* __restrict__ vbuf,
    const float* __restrict__ gbuf, float* __restrict__ ybuf)
{
    extern __shared__ char smraw[];
    AttnSmem& sm = *reinterpret_cast<AttnSmem*>(smraw);

    const int tb = blockIdx.x;             // t block 0..31
    const int bh = blockIdx.y;
    const int b  = bh / H_;
    const int h  = bh % H_;
    const int t0 = tb * 64;
    const int tid = threadIdx.x;
    const int tx = tid & 15;               // 0..15
    const int ty = tid >> 4;               // 0..15
    const float gamma = logf(1.0f - exp2f(-5.0f - (float)h));   // < 0

    const float* Qg = qk   + (size_t)b * T_ * (2 * C_) + h * KD_;
    const float* Kg = qk   + (size_t)b * T_ * (2 * C_) + C_ + h * KD_;
    const float* Vg = vbuf + (size_t)b * T_ * VBD_ + h * VD_;

    // Load Q tile (64 rows x 64 kd): 1024 float4
#pragma unroll
    for (int i = 0; i < 4; i++) {
        int idx = tid + i * 256;
        int r   = idx >> 4;
        int c4  = idx & 15;
        *(float4*)&sm.Qs[r][c4 * 4] =
            *(const float4*)&Qg[(size_t)(t0 + r) * (2 * C_) + c4 * 4];
    }
    if (tid < 64) sm.e1s[tid] = __expf(gamma * (float)tid);

    // accumulators: rows ty*4..+3, vd cols tx*8..+7
    float acc[4][8];
    float rden[4];
#pragma unroll
    for (int i = 0; i < 4; i++) {
        rden[i] = 0.f;
#pragma unroll
        for (int j = 0; j < 8; j++) acc[i][j] = 0.f;
    }

    for (int sb = 0; sb <= tb; sb++) {
        const int s0 = sb * 64;
        // K tile -> transposed KsT[kd][s]
#pragma unroll
        for (int i = 0; i < 4; i++) {
            int idx = tid + i * 256;
            int r   = idx >> 4;
            int c4  = idx & 15;
            float4 v = *(const float4*)&Kg[(size_t)(s0 + r) * (2 * C_) + c4 * 4];
            sm.KsT[c4 * 4 + 0][r] = v.x;
            sm.KsT[c4 * 4 + 1][r] = v.y;
            sm.KsT[c4 * 4 + 2][r] = v.z;
            sm.KsT[c4 * 4 + 3][r] = v.w;
        }
        // V tile (64 x 128)
#pragma unroll
        for (int i = 0; i < 8; i++) {
            int idx = tid + i * 256;
            int r   = idx >> 5;
            int c4  = idx & 31;
            *(float4*)&sm.Vs[r][c4 * 4] =
                *(const float4*)&Vg[(size_t)(s0 + r) * VBD_ + c4 * 4];
        }
        if (tid < 64) sm.e2s[tid] = __expf(gamma * (float)(t0 - s0 - tid));
        __syncthreads();

        // ---- Phase A: S[64][64] = (Q K^T) * decay, 4x4 per thread ----
        {
            float sacc[4][4];
#pragma unroll
            for (int i = 0; i < 4; i++)
#pragma unroll
                for (int j = 0; j < 4; j++) sacc[i][j] = 0.f;

#pragma unroll 16
            for (int k = 0; k < 64; k++) {
                float4 bk = *(const float4*)&sm.KsT[k][tx * 4];
                float a0 = sm.Qs[ty * 4 + 0][k];
                float a1 = sm.Qs[ty * 4 + 1][k];
                float a2 = sm.Qs[ty * 4 + 2][k];
                float a3 = sm.Qs[ty * 4 + 3][k];
                sacc[0][0] += a0 * bk.x; sacc[0][1] += a0 * bk.y;
                sacc[0][2] += a0 * bk.z; sacc[0][3] += a0 * bk.w;
                sacc[1][0] += a1 * bk.x; sacc[1][1] += a1 * bk.y;
                sacc[1][2] += a1 * bk.z; sacc[1][3] += a1 * bk.w;
                sacc[2][0] += a2 * bk.x; sacc[2][1] += a2 * bk.y;
                sacc[2][2] += a2 * bk.z; sacc[2][3] += a2 * bk.w;
                sacc[3][0] += a3 * bk.x; sacc[3][1] += a3 * bk.y;
                sacc[3][2] += a3 * bk.z; sacc[3][3] += a3 * bk.w;
            }
            const bool diag = (sb == tb);
#pragma unroll
            for (int i = 0; i < 4; i++) {
                int r = ty * 4 + i;
                float e1 = sm.e1s[r];
#pragma unroll
                for (int j = 0; j < 4; j++) {
                    int c = tx * 4 + j;
                    float dec = e1 * sm.e2s[c];
                    if (diag && c > r) dec = 0.f;
                    sm.Ss[r][c] = sacc[i][j] * dec;
                }
            }
        }
        __syncthreads();

        // ---- Phase B: acc += S @ V, denom += |S| ----
#pragma unroll 4
        for (int s = 0; s < 64; s++) {
            float sv0 = sm.Ss[ty * 4 + 0][s];
            float sv1 = sm.Ss[ty * 4 + 1][s];
            float sv2 = sm.Ss[ty * 4 + 2][s];
            float sv3 = sm.Ss[ty * 4 + 3][s];
            float4 v0 = *(const float4*)&sm.Vs[s][tx * 8];
            float4 v1 = *(const float4*)&sm.Vs[s][tx * 8 + 4];
            rden[0] += fabsf(sv0); rden[1] += fabsf(sv1);
            rden[2] += fabsf(sv2); rden[3] += fabsf(sv3);
            acc[0][0] += sv0 * v0.x; acc[0][1] += sv0 * v0.y;
            acc[0][2] += sv0 * v0.z; acc[0][3] += sv0 * v0.w;
            acc[0][4] += sv0 * v1.x; acc[0][5] += sv0 * v1.y;
            acc[0][6] += sv0 * v1.z; acc[0][7] += sv0 * v1.w;
            acc[1][0] += sv1 * v0.x; acc[1][1] += sv1 * v0.y;
            acc[1][2] += sv1 * v0.z; acc[1][3] += sv1 * v0.w;
            acc[1][4] += sv1 * v1.x; acc[1][5] += sv1 * v1.y;
            acc[1][6] += sv1 * v1.z; acc[1][7] += sv1 * v1.w;
            acc[2][0] += sv2 * v0.x; acc[2][1] += sv2 * v0.y;
            acc[2][2] += sv2 * v0.z; acc[2][3] += sv2 * v0.w;
            acc[2][4] += sv2 * v1.x; acc[2][5] += sv2 * v1.y;
            acc[2][6] += sv2 * v1.z; acc[2][7] += sv2 * v1.w;
            acc[3][0] += sv3 * v0.x; acc[3][1] += sv3 * v0.y;
            acc[3][2] += sv3 * v0.z; acc[3][3] += sv3 * v0.w;
            acc[3][4] += sv3 * v1.x; acc[3][5] += sv3 * v1.y;
            acc[3][6] += sv3 * v1.z; acc[3][7] += sv3 * v1.w;
        }
        __syncthreads();
    }

    // ---- Epilogue: scale/denom, RMSNorm over VD, gate, store y ----
    if (tx == 0) {
#pragma unroll
        for (int i = 0; i < 4; i++) sm.dnm[ty * 4 + i] = rden[i];
    }
    __syncthreads();

    const float inv_em1 = 1.0f / expm1f(gamma);
#pragma unroll
    for (int i = 0; i < 4; i++) {
        int r  = ty * 4 + i;
        int tg = t0 + r;
        float scl = sqrtf(expm1f(gamma * (float)(tg + 1)) * inv_em1);
        float d   = sm.dnm[r] / scl;
        d = fminf(fmaxf(d, 1.0f), 50000.0f);
        float inv = 1.0f / (scl * d);
        float ss = 0.f;
#pragma unroll
        for (int j = 0; j < 8; j++) {
            float v = acc[i][j] * inv;
            acc[i][j] = v;
            ss += v * v;
        }
        sm.ssq[r][tx] = ss;
    }
    __syncthreads();

#pragma unroll
    for (int i = 0; i < 4; i++) {
        int r  = ty * 4 + i;
        int tg = t0 + r;
        float ss = 0.f;
#pragma unroll
        for (int c = 0; c < 16; c++) ss += sm.ssq[r][c];
        float rms = rsqrtf(ss * (1.0f / 128.0f) + EPS_);
        size_t base = ((size_t)b * T_ + tg) * VBD_ + h * VD_ + tx * 8;
        float4 g0 = *(const float4*)&gbuf[base];
        float4 g1 = *(const float4*)&gbuf[base + 4];
        float4 y0, y1;
        y0.x = acc[i][0] * rms * g0.x; y0.y = acc[i][1] * rms * g0.y;
        y0.z = acc[i][2] * rms * g0.z; y0.w = acc[i][3] * rms * g0.w;
        y1.x = acc[i][4] * rms * g1.x; y1.y = acc[i][5] * rms * g1.y;
        y1.z = acc[i][6] * rms * g1.z; y1.w = acc[i][7] * rms * g1.w;
        *(float4*)&ybuf[base]     = y0;
        *(float4*)&ybuf[base + 4] = y1;
    }
}

// ---------------------------------------------------------------------------
extern "C" void kernel_launch(void* const* d_in, const int* in_sizes, int n_in,
                              void* d_out, int out_size)
{
    const float* x   = (const float*)d_in[0];
    const float* Wqk = (const float*)d_in[1];
    const float* bqk = (const float*)d_in[2];
    const float* Wv  = (const float*)d_in[3];
    const float* bv  = (const float*)d_in[4];
    const float* Wg  = (const float*)d_in[5];
    const float* bg  = (const float*)d_in[6];
    const float* Wo  = (const float*)d_in[7];
    const float* bo  = (const float*)d_in[8];
    float* out = (float*)d_out;

    float *qk, *v, *g, *y;
    cudaGetSymbolAddress((void**)&qk, g_qk);
    cudaGetSymbolAddress((void**)&v,  g_v);
    cudaGetSymbolAddress((void**)&g,  g_g);
    cudaGetSymbolAddress((void**)&y,  g_y);

    dim3 blk(256);

    // Projections: q|k, v, g
    sgemm_bias_k<<<dim3(2 * C_ / 128, M_ / 128), blk>>>(x, Wqk, bqk, qk, M_, 2 * C_, C_);
    sgemm_bias_k<<<dim3(VBD_ / 128, M_ / 128), blk>>>(x, Wv, bv, v, M_, VBD_, C_);
    sgemm_bias_k<<<dim3(VBD_ / 128, M_ / 128), blk>>>(x, Wg, bg, g, M_, VBD_, C_);

    // Fused retention attention + RMSNorm + gate
    int smem = (int)sizeof(AttnSmem);
    cudaFuncSetAttribute(retention_attn,
                         cudaFuncAttributeMaxDynamicSharedMemorySize, smem);
    retention_attn<<<dim3(T_ / 64, B_ * H_), blk, smem>>>(qk, v, g, y);

    // Output projection
    sgemm_bias_k<<<dim3(C_ / 128, M_ / 128), blk>>>(y, Wo, bo, out, M_, C_, 2 * C_);
}

// round 2
// speedup vs baseline: 1.6933x; 1.6933x over previous
#include <cuda_runtime.h>
#include <math.h>
#include <stdint.h>

// Problem constants
#define B_   2
#define T_   2048
#define C_   1024
#define H_   16
#define KD_  64
#define VD_  128
#define VBD_ 2048
#define M_   (B_ * T_)          // 4096
#define EPS_ 1.1920929e-07f     // np.finfo(np.float32).eps

// ---------------------------------------------------------------------------
// Scratch (device globals — no allocations allowed)
// ---------------------------------------------------------------------------
__device__ float g_qk[(size_t)M_ * 2 * C_];   // [4096, 2048]  q | k
__device__ float g_v [(size_t)M_ * VBD_];     // [4096, 2048]
__device__ float g_g [(size_t)M_ * VBD_];     // [4096, 2048]
__device__ float g_y [(size_t)M_ * VBD_];     // [4096, 2048]

// ===========================================================================
// TF32 tensor-core GEMM + bias: C[M,N] = A[M,K] @ W[K,N] + bias[N]
// BM=128, BN=128, BK=32, 256 threads (8 warps: 4 in m x 2 in n),
// warp tile 32x64, mma.sync.m16n8k8.tf32, 2-stage cp.async pipeline.
// Requires M%128==0, N%128==0, K%32==0.
// ===========================================================================
#define BM 128
#define BN 128
#define BK 32
#define ASTR 36    // A smem row stride (floats): [128][36]
#define BSTR 136   // B smem row stride (floats): [32][136]
#define A_STAGE (BM * ASTR)   // 4608 floats
#define B_STAGE (BK * BSTR)   // 4352 floats
#define GEMM_SMEM_BYTES ((2 * A_STAGE + 2 * B_STAGE) * 4)  // 71680

__device__ __forceinline__ void cp_async16(void* smem_ptr, const void* gmem_ptr) {
    unsigned sa = (unsigned)__cvta_generic_to_shared(smem_ptr);
    asm volatile("cp.async.cg.shared.global [%0], [%1], 16;\n" :: "r"(sa), "l"(gmem_ptr));
}
__device__ __forceinline__ void cp_commit() {
    asm volatile("cp.async.commit_group;\n");
}

__device__ __forceinline__ uint32_t f2tf32(float x) {
    uint32_t r;
    asm("cvt.rna.tf32.f32 %0, %1;\n" : "=r"(r) : "f"(x));
    return r;
}

__device__ __forceinline__ void mma_tf32(float d[4], const uint32_t a[4], const uint32_t b[2]) {
    asm volatile(
        "mma.sync.aligned.m16n8k8.row.col.f32.tf32.tf32.f32 "
        "{%0,%1,%2,%3}, {%4,%5,%6,%7}, {%8,%9}, {%0,%1,%2,%3};\n"
        : "+f"(d[0]), "+f"(d[1]), "+f"(d[2]), "+f"(d[3])
        : "r"(a[0]), "r"(a[1]), "r"(a[2]), "r"(a[3]), "r"(b[0]), "r"(b[1]));
}

__global__ __launch_bounds__(256) void tf32_gemm_bias(
    const float* __restrict__ A, const float* __restrict__ W,
    const float* __restrict__ bias, float* __restrict__ Cout,
    int M, int N, int K)
{
    extern __shared__ float smem[];
    float* As = smem;                  // [2][128][ASTR]
    float* Bs = smem + 2 * A_STAGE;    // [2][32][BSTR]

    const int tid  = threadIdx.x;
    const int wid  = tid >> 5;
    const int lane = tid & 31;
    const int gid  = lane >> 2;   // 0..7
    const int tg   = lane & 3;    // 0..3
    const int wm   = (wid & 3) * 32;   // warp m offset
    const int wn   = (wid >> 2) * 64;  // warp n offset
    const int m0   = blockIdx.y * BM;
    const int n0   = blockIdx.x * BN;

    float acc[2][8][4];
#pragma unroll
    for (int mi = 0; mi < 2; mi++)
#pragma unroll
        for (int ni = 0; ni < 8; ni++)
#pragma unroll
            for (int r = 0; r < 4; r++) acc[mi][ni][r] = 0.f;

    // Global->smem stage loader (cp.async, 4 x 16B per thread for A and B)
    const int a_row = 0; (void)a_row;
    const int nk = K / BK;

    // precompute per-thread load coordinates
    // A tile: 128x32 = 1024 float4; idx = tid + i*256: row=idx>>3, c4=idx&7
    // B tile: 32x128 = 1024 float4; idx = tid + i*256: row=idx>>5, c4=idx&31
#define LOAD_STAGE(stg, kb)                                                       \
    {                                                                             \
        float* Asd = As + (stg) * A_STAGE;                                        \
        float* Bsd = Bs + (stg) * B_STAGE;                                        \
        _Pragma("unroll")                                                         \
        for (int i = 0; i < 4; i++) {                                             \
            int idx = tid + i * 256;                                              \
            int row = idx >> 3, c4 = idx & 7;                                     \
            cp_async16(Asd + row * ASTR + c4 * 4,                                 \
                       A + (size_t)(m0 + row) * K + (kb) + c4 * 4);               \
        }                                                                         \
        _Pragma("unroll")                                                         \
        for (int i = 0; i < 4; i++) {                                             \
            int idx = tid + i * 256;                                              \
            int row = idx >> 5, c4 = idx & 31;                                    \
            cp_async16(Bsd + row * BSTR + c4 * 4,                                 \
                       W + (size_t)((kb) + row) * N + n0 + c4 * 4);               \
        }                                                                         \
        cp_commit();                                                              \
    }

    LOAD_STAGE(0, 0);

    for (int kb = 0; kb < nk; kb++) {
        if (kb + 1 < nk) {
            LOAD_STAGE((kb + 1) & 1, (kb + 1) * BK);
            asm volatile("cp.async.wait_group 1;\n");
        } else {
            asm volatile("cp.async.wait_group 0;\n");
        }
        __syncthreads();

        const float* Asb = As + (kb & 1) * A_STAGE;
        const float* Bsb = Bs + (kb & 1) * B_STAGE;

#pragma unroll
        for (int ks = 0; ks < 4; ks++) {
            const int k = ks * 8;
            uint32_t af[2][4], bf[8][2];
#pragma unroll
            for (int mi = 0; mi < 2; mi++) {
                const float* ap = Asb + (wm + mi * 16) * ASTR + k + tg;
                af[mi][0] = f2tf32(ap[gid * ASTR]);
                af[mi][1] = f2tf32(ap[(gid + 8) * ASTR]);
                af[mi][2] = f2tf32(ap[gid * ASTR + 4]);
                af[mi][3] = f2tf32(ap[(gid + 8) * ASTR + 4]);
            }
#pragma unroll
            for (int ni = 0; ni < 8; ni++) {
                const float* bp = Bsb + (k + tg) * BSTR + wn + ni * 8 + gid;
                bf[ni][0] = f2tf32(bp[0]);
                bf[ni][1] = f2tf32(bp[4 * BSTR]);
            }
#pragma unroll
            for (int mi = 0; mi < 2; mi++)
#pragma unroll
                for (int ni = 0; ni < 8; ni++)
                    mma_tf32(acc[mi][ni], af[mi], bf[ni]);
        }
        __syncthreads();
    }

    // Epilogue: bias add + store (float2 per fragment row)
#pragma unroll
    for (int mi = 0; mi < 2; mi++) {
#pragma unroll
        for (int ni = 0; ni < 8; ni++) {
            int row0 = m0 + wm + mi * 16 + gid;
            int col  = n0 + wn + ni * 8 + tg * 2;
            float b0 = bias[col], b1 = bias[col + 1];
            float2 v0 = make_float2(acc[mi][ni][0] + b0, acc[mi][ni][1] + b1);
            float2 v1 = make_float2(acc[mi][ni][2] + b0, acc[mi][ni][3] + b1);
            *(float2*)&Cout[(size_t)row0 * N + col]       = v0;
            *(float2*)&Cout[(size_t)(row0 + 8) * N + col] = v1;
        }
    }
}

// ---------------------------------------------------------------------------
// Retention attention, fused normalization + gate. (unchanged from R1)
// ---------------------------------------------------------------------------
struct AttnSmem {
    float Qs [64][68];
    float KsT[64][68];
    float Ss [64][65];
    float Vs [64][128];
    float e1s[64];
    float e2s[64];
    float dnm[64];
    float ssq[64][16];
};

__global__ __launch_bounds__(256) void retention_attn(
    const float* __restrict__ qk, const float* __restrict__ vbuf,
    const float* __restrict__ gbuf, float* __restrict__ ybuf)
{
    extern __shared__ char smraw[];
    AttnSmem& sm = *reinterpret_cast<AttnSmem*>(smraw);

    const int tb = blockIdx.x;
    const int bh = blockIdx.y;
    const int b  = bh / H_;
    const int h  = bh % H_;
    const int t0 = tb * 64;
    const int tid = threadIdx.x;
    const int tx = tid & 15;
    const int ty = tid >> 4;
    const float gamma = logf(1.0f - exp2f(-5.0f - (float)h));

    const float* Qg = qk   + (size_t)b * T_ * (2 * C_) + h * KD_;
    const float* Kg = qk   + (size_t)b * T_ * (2 * C_) + C_ + h * KD_;
    const float* Vg = vbuf + (size_t)b * T_ * VBD_ + h * VD_;

#pragma unroll
    for (int i = 0; i < 4; i++) {
        int idx = tid + i * 256;
        int r   = idx >> 4;
        int c4  = idx & 15;
        *(float4*)&sm.Qs[r][c4 * 4] =
            *(const float4*)&Qg[(size_t)(t0 + r) * (2 * C_) + c4 * 4];
    }
    if (tid < 64) sm.e1s[tid] = __expf(gamma * (float)tid);

    float acc[4][8];
    float rden[4];
#pragma unroll
    for (int i = 0; i < 4; i++) {
        rden[i] = 0.f;
#pragma unroll
        for (int j = 0; j < 8; j++) acc[i][j] = 0.f;
    }

    for (int sb = 0; sb <= tb; sb++) {
        const int s0 = sb * 64;
#pragma unroll
        for (int i = 0; i < 4; i++) {
            int idx = tid + i * 256;
            int r   = idx >> 4;
            int c4  = idx & 15;
            float4 v = *(const float4*)&Kg[(size_t)(s0 + r) * (2 * C_) + c4 * 4];
            sm.KsT[c4 * 4 + 0][r] = v.x;
            sm.KsT[c4 * 4 + 1][r] = v.y;
            sm.KsT[c4 * 4 + 2][r] = v.z;
            sm.KsT[c4 * 4 + 3][r] = v.w;
        }
#pragma unroll
        for (int i = 0; i < 8; i++) {
            int idx = tid + i * 256;
            int r   = idx >> 5;
            int c4  = idx & 31;
            *(float4*)&sm.Vs[r][c4 * 4] =
                *(const float4*)&Vg[(size_t)(s0 + r) * VBD_ + c4 * 4];
        }
        if (tid < 64) sm.e2s[tid] = __expf(gamma * (float)(t0 - s0 - tid));
        __syncthreads();

        {
            float sacc[4][4];
#pragma unroll
            for (int i = 0; i < 4; i++)
#pragma unroll
                for (int j = 0; j < 4; j++) sacc[i][j] = 0.f;

#pragma unroll 16
            for (int k = 0; k < 64; k++) {
                float4 bk = *(const float4*)&sm.KsT[k][tx * 4];
                float a0 = sm.Qs[ty * 4 + 0][k];
                float a1 = sm.Qs[ty * 4 + 1][k];
                float a2 = sm.Qs[ty * 4 + 2][k];
                float a3 = sm.Qs[ty * 4 + 3][k];
                sacc[0][0] += a0 * bk.x; sacc[0][1] += a0 * bk.y;
                sacc[0][2] += a0 * bk.z; sacc[0][3] += a0 * bk.w;
                sacc[1][0] += a1 * bk.x; sacc[1][1] += a1 * bk.y;
                sacc[1][2] += a1 * bk.z; sacc[1][3] += a1 * bk.w;
                sacc[2][0] += a2 * bk.x; sacc[2][1] += a2 * bk.y;
                sacc[2][2] += a2 * bk.z; sacc[2][3] += a2 * bk.w;
                sacc[3][0] += a3 * bk.x; sacc[3][1] += a3 * bk.y;
                sacc[3][2] += a3 * bk.z; sacc[3][3] += a3 * bk.w;
            }
            const bool diag = (sb == tb);
#pragma unroll
            for (int i = 0; i < 4; i++) {
                int r = ty * 4 + i;
                float e1 = sm.e1s[r];
#pragma unroll
                for (int j = 0; j < 4; j++) {
                    int c = tx * 4 + j;
                    float dec = e1 * sm.e2s[c];
                    if (diag && c > r) dec = 0.f;
                    sm.Ss[r][c] = sacc[i][j] * dec;
                }
            }
        }
        __syncthreads();

#pragma unroll 4
        for (int s = 0; s < 64; s++) {
            float sv0 = sm.Ss[ty * 4 + 0][s];
            float sv1 = sm.Ss[ty * 4 + 1][s];
            float sv2 = sm.Ss[ty * 4 + 2][s];
            float sv3 = sm.Ss[ty * 4 + 3][s];
            float4 v0 = *(const float4*)&sm.Vs[s][tx * 8];
            float4 v1 = *(const float4*)&sm.Vs[s][tx * 8 + 4];
            rden[0] += fabsf(sv0); rden[1] += fabsf(sv1);
            rden[2] += fabsf(sv2); rden[3] += fabsf(sv3);
            acc[0][0] += sv0 * v0.x; acc[0][1] += sv0 * v0.y;
            acc[0][2] += sv0 * v0.z; acc[0][3] += sv0 * v0.w;
            acc[0][4] += sv0 * v1.x; acc[0][5] += sv0 * v1.y;
            acc[0][6] += sv0 * v1.z; acc[0][7] += sv0 * v1.w;
            acc[1][0] += sv1 * v0.x; acc[1][1] += sv1 * v0.y;
            acc[1][2] += sv1 * v0.z; acc[1][3] += sv1 * v0.w;
            acc[1][4] += sv1 * v1.x; acc[1][5] += sv1 * v1.y;
            acc[1][6] += sv1 * v1.z; acc[1][7] += sv1 * v1.w;
            acc[2][0] += sv2 * v0.x; acc[2][1] += sv2 * v0.y;
            acc[2][2] += sv2 * v0.z; acc[2][3] += sv2 * v0.w;
            acc[2][4] += sv2 * v1.x; acc[2][5] += sv2 * v1.y;
            acc[2][6] += sv2 * v1.z; acc[2][7] += sv2 * v1.w;
            acc[3][0] += sv3 * v0.x; acc[3][1] += sv3 * v0.y;
            acc[3][2] += sv3 * v0.z; acc[3][3] += sv3 * v0.w;
            acc[3][4] += sv3 * v1.x; acc[3][5] += sv3 * v1.y;
            acc[3][6] += sv3 * v1.z; acc[3][7] += sv3 * v1.w;
        }
        __syncthreads();
    }

    if (tx == 0) {
#pragma unroll
        for (int i = 0; i < 4; i++) sm.dnm[ty * 4 + i] = rden[i];
    }
    __syncthreads();

    const float inv_em1 = 1.0f / expm1f(gamma);
#pragma unroll
    for (int i = 0; i < 4; i++) {
        int r  = ty * 4 + i;
        int tg = t0 + r;
        float scl = sqrtf(expm1f(gamma * (float)(tg + 1)) * inv_em1);
        float d   = sm.dnm[r] / scl;
        d = fminf(fmaxf(d, 1.0f), 50000.0f);
        float inv = 1.0f / (scl * d);
        float ss = 0.f;
#pragma unroll
        for (int j = 0; j < 8; j++) {
            float v = acc[i][j] * inv;
            acc[i][j] = v;
            ss += v * v;
        }
        sm.ssq[r][tx] = ss;
    }
    __syncthreads();

#pragma unroll
    for (int i = 0; i < 4; i++) {
        int r  = ty * 4 + i;
        int tg = t0 + r;
        float ss = 0.f;
#pragma unroll
        for (int c = 0; c < 16; c++) ss += sm.ssq[r][c];
        float rms = rsqrtf(ss * (1.0f / 128.0f) + EPS_);
        size_t base = ((size_t)b * T_ + tg) * VBD_ + h * VD_ + tx * 8;
        float4 g0 = *(const float4*)&gbuf[base];
        float4 g1 = *(const float4*)&gbuf[base + 4];
        float4 y0, y1;
        y0.x = acc[i][0] * rms * g0.x; y0.y = acc[i][1] * rms * g0.y;
        y0.z = acc[i][2] * rms * g0.z; y0.w = acc[i][3] * rms * g0.w;
        y1.x = acc[i][4] * rms * g1.x; y1.y = acc[i][5] * rms * g1.y;
        y1.z = acc[i][6] * rms * g1.z; y1.w = acc[i][7] * rms * g1.w;
        *(float4*)&ybuf[base]     = y0;
        *(float4*)&ybuf[base + 4] = y1;
    }
}

// ---------------------------------------------------------------------------
extern "C" void kernel_launch(void* const* d_in, const int* in_sizes, int n_in,
                              void* d_out, int out_size)
{
    const float* x   = (const float*)d_in[0];
    const float* Wqk = (const float*)d_in[1];
    const float* bqk = (const float*)d_in[2];
    const float* Wv  = (const float*)d_in[3];
    const float* bv  = (const float*)d_in[4];
    const float* Wg  = (const float*)d_in[5];
    const float* bg  = (const float*)d_in[6];
    const float* Wo  = (const float*)d_in[7];
    const float* bo  = (const float*)d_in[8];
    float* out = (float*)d_out;

    float *qk, *v, *g, *y;
    cudaGetSymbolAddress((void**)&qk, g_qk);
    cudaGetSymbolAddress((void**)&v,  g_v);
    cudaGetSymbolAddress((void**)&g,  g_g);
    cudaGetSymbolAddress((void**)&y,  g_y);

    dim3 blk(256);

    static bool attr_set = false;
    if (!attr_set) {
        cudaFuncSetAttribute(tf32_gemm_bias,
                             cudaFuncAttributeMaxDynamicSharedMemorySize, GEMM_SMEM_BYTES);
        cudaFuncSetAttribute(retention_attn,
                             cudaFuncAttributeMaxDynamicSharedMemorySize, (int)sizeof(AttnSmem));
        attr_set = true;
    }

    // Projections: q|k, v, g   (tensor-core tf32)
    tf32_gemm_bias<<<dim3(2 * C_ / BN, M_ / BM), blk, GEMM_SMEM_BYTES>>>(x, Wqk, bqk, qk, M_, 2 * C_, C_);
    tf32_gemm_bias<<<dim3(VBD_ / BN, M_ / BM), blk, GEMM_SMEM_BYTES>>>(x, Wv, bv, v, M_, VBD_, C_);
    tf32_gemm_bias<<<dim3(VBD_ / BN, M_ / BM), blk, GEMM_SMEM_BYTES>>>(x, Wg, bg, g, M_, VBD_, C_);

    // Fused retention attention + RMSNorm + gate
    retention_attn<<<dim3(T_ / 64, B_ * H_), blk, (int)sizeof(AttnSmem)>>>(qk, v, g, y);

    // Output projection
    tf32_gemm_bias<<<dim3(C_ / BN, M_ / BM), blk, GEMM_SMEM_BYTES>>>(y, Wo, bo, out, M_, C_, 2 * C_);
}

// round 3
// speedup vs baseline: 3.2553x; 1.9224x over previous
#include <cuda_runtime.h>
#include <math.h>
#include <stdint.h>

// Problem constants
#define B_   2
#define T_   2048
#define C_   1024
#define H_   16
#define KD_  64
#define VD_  128
#define VBD_ 2048
#define M_   (B_ * T_)          // 4096
#define EPS_ 1.1920929e-07f

// ---------------------------------------------------------------------------
// Scratch (device globals)
// ---------------------------------------------------------------------------
__device__ float g_qk[(size_t)M_ * 2 * C_];
__device__ float g_v [(size_t)M_ * VBD_];
__device__ float g_g [(size_t)M_ * VBD_];
__device__ float g_y [(size_t)M_ * VBD_];

// ===========================================================================
// Shared helpers
// ===========================================================================
__device__ __forceinline__ void cp_async16(void* smem_ptr, const void* gmem_ptr) {
    unsigned sa = (unsigned)__cvta_generic_to_shared(smem_ptr);
    asm volatile("cp.async.cg.shared.global [%0], [%1], 16;\n" :: "r"(sa), "l"(gmem_ptr));
}
__device__ __forceinline__ void cp_commit() {
    asm volatile("cp.async.commit_group;\n");
}
__device__ __forceinline__ uint32_t f2tf32(float x) {
    uint32_t r;
    asm("cvt.rna.tf32.f32 %0, %1;\n" : "=r"(r) : "f"(x));
    return r;
}
__device__ __forceinline__ float tf32f(float x) {
    return __uint_as_float(f2tf32(x));
}
__device__ __forceinline__ void mma_tf32(float d[4], const uint32_t a[4], const uint32_t b[2]) {
    asm volatile(
        "mma.sync.aligned.m16n8k8.row.col.f32.tf32.tf32.f32 "
        "{%0,%1,%2,%3}, {%4,%5,%6,%7}, {%8,%9}, {%0,%1,%2,%3};\n"
        : "+f"(d[0]), "+f"(d[1]), "+f"(d[2]), "+f"(d[3])
        : "r"(a[0]), "r"(a[1]), "r"(a[2]), "r"(a[3]), "r"(b[0]), "r"(b[1]));
}

// ===========================================================================
// TF32 tensor-core GEMM + bias (unchanged from R2)
// ===========================================================================
#define BM 128
#define BN 128
#define BK 32
#define ASTR 36
#define BSTR 136
#define A_STAGE (BM * ASTR)
#define B_STAGE (BK * BSTR)
#define GEMM_SMEM_BYTES ((2 * A_STAGE + 2 * B_STAGE) * 4)

__global__ __launch_bounds__(256) void tf32_gemm_bias(
    const float* __restrict__ A, const float* __restrict__ W,
    const float* __restrict__ bias, float* __restrict__ Cout,
    int M, int N, int K)
{
    extern __shared__ float smem[];
    float* As = smem;
    float* Bs = smem + 2 * A_STAGE;

    const int tid  = threadIdx.x;
    const int wid  = tid >> 5;
    const int lane = tid & 31;
    const int gid  = lane >> 2;
    const int tg   = lane & 3;
    const int wm   = (wid & 3) * 32;
    const int wn   = (wid >> 2) * 64;
    const int m0   = blockIdx.y * BM;
    const int n0   = blockIdx.x * BN;

    float acc[2][8][4];
#pragma unroll
    for (int mi = 0; mi < 2; mi++)
#pragma unroll
        for (int ni = 0; ni < 8; ni++)
#pragma unroll
            for (int r = 0; r < 4; r++) acc[mi][ni][r] = 0.f;

    const int nk = K / BK;

#define LOAD_STAGE(stg, kb)                                                       \
    {                                                                             \
        float* Asd = As + (stg) * A_STAGE;                                        \
        float* Bsd = Bs + (stg) * B_STAGE;                                        \
        _Pragma("unroll")                                                         \
        for (int i = 0; i < 4; i++) {                                             \
            int idx = tid + i * 256;                                              \
            int row = idx >> 3, c4 = idx & 7;                                     \
            cp_async16(Asd + row * ASTR + c4 * 4,                                 \
                       A + (size_t)(m0 + row) * K + (kb) + c4 * 4);               \
        }                                                                         \
        _Pragma("unroll")                                                         \
        for (int i = 0; i < 4; i++) {                                             \
            int idx = tid + i * 256;                                              \
            int row = idx >> 5, c4 = idx & 31;                                    \
            cp_async16(Bsd + row * BSTR + c4 * 4,                                 \
                       W + (size_t)((kb) + row) * N + n0 + c4 * 4);               \
        }                                                                         \
        cp_commit();                                                              \
    }

    LOAD_STAGE(0, 0);

    for (int kb = 0; kb < nk; kb++) {
        if (kb + 1 < nk) {
            LOAD_STAGE((kb + 1) & 1, (kb + 1) * BK);
            asm volatile("cp.async.wait_group 1;\n");
        } else {
            asm volatile("cp.async.wait_group 0;\n");
        }
        __syncthreads();

        const float* Asb = As + (kb & 1) * A_STAGE;
        const float* Bsb = Bs + (kb & 1) * B_STAGE;

#pragma unroll
        for (int ks = 0; ks < 4; ks++) {
            const int k = ks * 8;
            uint32_t af[2][4], bf[8][2];
#pragma unroll
            for (int mi = 0; mi < 2; mi++) {
                const float* ap = Asb + (wm + mi * 16) * ASTR + k + tg;
                af[mi][0] = f2tf32(ap[gid * ASTR]);
                af[mi][1] = f2tf32(ap[(gid + 8) * ASTR]);
                af[mi][2] = f2tf32(ap[gid * ASTR + 4]);
                af[mi][3] = f2tf32(ap[(gid + 8) * ASTR + 4]);
            }
#pragma unroll
            for (int ni = 0; ni < 8; ni++) {
                const float* bp = Bsb + (k + tg) * BSTR + wn + ni * 8 + gid;
                bf[ni][0] = f2tf32(bp[0]);
                bf[ni][1] = f2tf32(bp[4 * BSTR]);
            }
#pragma unroll
            for (int mi = 0; mi < 2; mi++)
#pragma unroll
                for (int ni = 0; ni < 8; ni++)
                    mma_tf32(acc[mi][ni], af[mi], bf[ni]);
        }
        __syncthreads();
    }

#pragma unroll
    for (int mi = 0; mi < 2; mi++) {
#pragma unroll
        for (int ni = 0; ni < 8; ni++) {
            int row0 = m0 + wm + mi * 16 + gid;
            int col  = n0 + wn + ni * 8 + tg * 2;
            float b0 = bias[col], b1 = bias[col + 1];
            float2 v0 = make_float2(acc[mi][ni][0] + b0, acc[mi][ni][1] + b1);
            float2 v1 = make_float2(acc[mi][ni][2] + b0, acc[mi][ni][3] + b1);
            *(float2*)&Cout[(size_t)row0 * N + col]       = v0;
            *(float2*)&Cout[(size_t)(row0 + 8) * N + col] = v1;
        }
    }
}

// ===========================================================================
// Tensor-core retention attention + fused RMSNorm + gate.
// 64 q-rows per CTA, 256 threads (8 warps: 4 row-groups x 2 col-halves).
// Decay folded into Q (e1) and K (e2) at load -> S = Q'K'^T via tf32 MMA.
// Q fragments live in registers for the whole CTA.
// ===========================================================================
struct AttnSmemTC {
    float QS[64][68];    // Q' tile, later aliased as S tile
    float Ks[64][68];    // K' tile [s][kd], tf32-rounded
    float Vs[64][136];   // V tile [s][vd], tf32-rounded (pad 8 mod 32 banks)
    float red[64][8];    // denominator partials
    float ssq[64][8];    // rms partials
};
#define ATTN_SMEM_BYTES ((int)sizeof(AttnSmemTC))

__global__ __launch_bounds__(256) void retention_attn_tc(
    const float* __restrict__ qk, const float* __restrict__ vbuf,
    const float* __restrict__ gbuf, float* __restrict__ ybuf)
{
    extern __shared__ char smraw[];
    AttnSmemTC& sm = *reinterpret_cast<AttnSmemTC*>(smraw);

    const int tb = (T_ / 64 - 1) - blockIdx.x;   // heavy tiles first
    const int bh = blockIdx.y;
    const int b  = bh >> 4;
    const int h  = bh & 15;
    const int t0 = tb * 64;
    const int tid  = threadIdx.x;
    const int wid  = tid >> 5;
    const int lane = tid & 31;
    const int gid  = lane >> 2;    // 0..7
    const int tg   = lane & 3;     // 0..3
    const int wm   = (wid & 3) * 16;
    const int wh   = wid >> 2;     // 0/1
    const float gamma = logf(1.0f - exp2f(-5.0f - (float)h));

    const float* Qg = qk   + (size_t)b * T_ * (2 * C_) + h * KD_;
    const float* Kg = qk   + (size_t)b * T_ * (2 * C_) + C_ + h * KD_;
    const float* Vg = vbuf + (size_t)b * T_ * VBD_ + h * VD_;

    // ---- Load Q tile with e1 fold, tf32-rounded ----
#pragma unroll
    for (int i = 0; i < 4; i++) {
        int idx = tid + i * 256;
        int r   = idx >> 4;
        int c4  = idx & 15;
        float4 q = *(const float4*)&Qg[(size_t)(t0 + r) * (2 * C_) + c4 * 4];
        float e1 = expf(gamma * (float)r);
        float4 o;
        o.x = tf32f(q.x * e1); o.y = tf32f(q.y * e1);
        o.z = tf32f(q.z * e1); o.w = tf32f(q.w * e1);
        *(float4*)&sm.QS[r][c4 * 4] = o;
    }
    __syncthreads();

    // ---- Hoist Q fragments into registers (invariant across s-tiles) ----
    uint32_t qf[8][4];
#pragma unroll
    for (int ks = 0; ks < 8; ks++) {
        qf[ks][0] = __float_as_uint(sm.QS[wm + gid    ][ks * 8 + tg]);
        qf[ks][1] = __float_as_uint(sm.QS[wm + gid + 8][ks * 8 + tg]);
        qf[ks][2] = __float_as_uint(sm.QS[wm + gid    ][ks * 8 + tg + 4]);
        qf[ks][3] = __float_as_uint(sm.QS[wm + gid + 8][ks * 8 + tg + 4]);
    }

    float oacc[8][4];
#pragma unroll
    for (int ni = 0; ni < 8; ni++)
#pragma unroll
        for (int r = 0; r < 4; r++) oacc[ni][r] = 0.f;
    float rden0 = 0.f, rden1 = 0.f;

    for (int sb = 0; sb <= tb; sb++) {
        const int s0 = sb * 64;

        // K' tile: e2 fold + tf32 round
#pragma unroll
        for (int i = 0; i < 4; i++) {
            int idx = tid + i * 256;
            int r   = idx >> 4;
            int c4  = idx & 15;
            float4 k = *(const float4*)&Kg[(size_t)(s0 + r) * (2 * C_) + c4 * 4];
            float e2 = expf(gamma * (float)(t0 - (s0 + r)));
            float4 o;
            o.x = tf32f(k.x * e2); o.y = tf32f(k.y * e2);
            o.z = tf32f(k.z * e2); o.w = tf32f(k.w * e2);
            *(float4*)&sm.Ks[r][c4 * 4] = o;
        }
        // V tile, tf32 round
#pragma unroll
        for (int i = 0; i < 8; i++) {
            int idx = tid + i * 256;
            int r   = idx >> 5;
            int c4  = idx & 31;
            float4 v = *(const float4*)&Vg[(size_t)(s0 + r) * VBD_ + c4 * 4];
            float4 o;
            o.x = tf32f(v.x); o.y = tf32f(v.y);
            o.z = tf32f(v.z); o.w = tf32f(v.w);
            *(float4*)&sm.Vs[r][c4 * 4] = o;
        }
        __syncthreads();

        // ---- QK^T: warp computes S[wm:wm+16, wh*32 : wh*32+32] ----
        float sacc[4][4];
#pragma unroll
        for (int ni = 0; ni < 4; ni++)
#pragma unroll
            for (int r = 0; r < 4; r++) sacc[ni][r] = 0.f;

#pragma unroll
        for (int ks = 0; ks < 8; ks++) {
#pragma unroll
            for (int ni = 0; ni < 4; ni++) {
                int n = wh * 32 + ni * 8 + gid;
                uint32_t bb[2];
                bb[0] = __float_as_uint(sm.Ks[n][ks * 8 + tg]);
                bb[1] = __float_as_uint(sm.Ks[n][ks * 8 + tg + 4]);
                mma_tf32(sacc[ni], qf[ks], bb);
            }
        }

        // diag mask, rden partials, write S (tf32) to smem (aliases QS)
        const bool diag = (sb == tb);
        const int r0 = wm + gid, r1 = r0 + 8;
#pragma unroll
        for (int ni = 0; ni < 4; ni++) {
            int c0 = wh * 32 + ni * 8 + 2 * tg;
            if (diag) {
                if (c0     > r0) sacc[ni][0] = 0.f;
                if (c0 + 1 > r0) sacc[ni][1] = 0.f;
                if (c0     > r1) sacc[ni][2] = 0.f;
                if (c0 + 1 > r1) sacc[ni][3] = 0.f;
            }
            rden0 += fabsf(sacc[ni][0]) + fabsf(sacc[ni][1]);
            rden1 += fabsf(sacc[ni][2]) + fabsf(sacc[ni][3]);
            float2 w0 = make_float2(tf32f(sacc[ni][0]), tf32f(sacc[ni][1]));
            float2 w1 = make_float2(tf32f(sacc[ni][2]), tf32f(sacc[ni][3]));
            *(float2*)&sm.QS[r0][c0] = w0;
            *(float2*)&sm.QS[r1][c0] = w1;
        }
        __syncthreads();

        // ---- S @ V: warp computes O[wm:wm+16, wh*64 : wh*64+64] ----
#pragma unroll
        for (int ks = 0; ks < 8; ks++) {
            uint32_t aa[4];
            aa[0] = __float_as_uint(sm.QS[r0][ks * 8 + tg]);
            aa[1] = __float_as_uint(sm.QS[r1][ks * 8 + tg]);
            aa[2] = __float_as_uint(sm.QS[r0][ks * 8 + tg + 4]);
            aa[3] = __float_as_uint(sm.QS[r1][ks * 8 + tg + 4]);
#pragma unroll
            for (int ni = 0; ni < 8; ni++) {
                int n = wh * 64 + ni * 8 + gid;
                uint32_t bb[2];
                bb[0] = __float_as_uint(sm.Vs[ks * 8 + tg][n]);
                bb[1] = __float_as_uint(sm.Vs[ks * 8 + tg + 4][n]);
                mma_tf32(oacc[ni], aa, bb);
            }
        }
        __syncthreads();
    }

    // ---- Epilogue ----
    const int r0 = wm + gid, r1 = r0 + 8;
    sm.red[r0][wh * 4 + tg] = rden0;
    sm.red[r1][wh * 4 + tg] = rden1;
    __syncthreads();

    float dn0 = 0.f, dn1 = 0.f;
#pragma unroll
    for (int j = 0; j < 8; j++) { dn0 += sm.red[r0][j]; dn1 += sm.red[r1][j]; }

    const float inv_em1 = 1.0f / expm1f(gamma);
    float scl0 = sqrtf(expm1f(gamma * (float)(t0 + r0 + 1)) * inv_em1);
    float scl1 = sqrtf(expm1f(gamma * (float)(t0 + r1 + 1)) * inv_em1);
    float d0 = fminf(fmaxf(dn0 / scl0, 1.0f), 50000.0f);
    float d1 = fminf(fmaxf(dn1 / scl1, 1.0f), 50000.0f);
    float inv0 = 1.0f / (scl0 * d0);
    float inv1 = 1.0f / (scl1 * d1);

    float ss0 = 0.f, ss1 = 0.f;
#pragma unroll
    for (int ni = 0; ni < 8; ni++) {
        oacc[ni][0] *= inv0; oacc[ni][1] *= inv0;
        oacc[ni][2] *= inv1; oacc[ni][3] *= inv1;
        ss0 += oacc[ni][0] * oacc[ni][0] + oacc[ni][1] * oacc[ni][1];
        ss1 += oacc[ni][2] * oacc[ni][2] + oacc[ni][3] * oacc[ni][3];
    }
    sm.ssq[r0][wh * 4 + tg] = ss0;
    sm.ssq[r1][wh * 4 + tg] = ss1;
    __syncthreads();

    float t0s = 0.f, t1s = 0.f;
#pragma unroll
    for (int j = 0; j < 8; j++) { t0s += sm.ssq[r0][j]; t1s += sm.ssq[r1][j]; }
    float rms0 = rsqrtf(t0s * (1.0f / 128.0f) + EPS_);
    float rms1 = rsqrtf(t1s * (1.0f / 128.0f) + EPS_);

#pragma unroll
    for (int ni = 0; ni < 8; ni++) {
        int col = h * VD_ + wh * 64 + ni * 8 + 2 * tg;
        size_t b0i = ((size_t)b * T_ + t0 + r0) * VBD_ + col;
        size_t b1i = ((size_t)b * T_ + t0 + r1) * VBD_ + col;
        float2 ga = *(const float2*)&gbuf[b0i];
        float2 gb = *(const float2*)&gbuf[b1i];
        float2 y0 = make_float2(oacc[ni][0] * rms0 * ga.x, oacc[ni][1] * rms0 * ga.y);
        float2 y1 = make_float2(oacc[ni][2] * rms1 * gb.x, oacc[ni][3] * rms1 * gb.y);
        *(float2*)&ybuf[b0i] = y0;
        *(float2*)&ybuf[b1i] = y1;
    }
}

// ---------------------------------------------------------------------------
extern "C" void kernel_launch(void* const* d_in, const int* in_sizes, int n_in,
                              void* d_out, int out_size)
{
    const float* x   = (const float*)d_in[0];
    const float* Wqk = (const float*)d_in[1];
    const float* bqk = (const float*)d_in[2];
    const float* Wv  = (const float*)d_in[3];
    const float* bv  = (const float*)d_in[4];
    const float* Wg  = (const float*)d_in[5];
    const float* bg  = (const float*)d_in[6];
    const float* Wo  = (const float*)d_in[7];
    const float* bo  = (const float*)d_in[8];
    float* out = (float*)d_out;

    float *qk, *v, *g, *y;
    cudaGetSymbolAddress((void**)&qk, g_qk);
    cudaGetSymbolAddress((void**)&v,  g_v);
    cudaGetSymbolAddress((void**)&g,  g_g);
    cudaGetSymbolAddress((void**)&y,  g_y);

    dim3 blk(256);

    static bool attr_set = false;
    if (!attr_set) {
        cudaFuncSetAttribute(tf32_gemm_bias,
                             cudaFuncAttributeMaxDynamicSharedMemorySize, GEMM_SMEM_BYTES);
        cudaFuncSetAttribute(retention_attn_tc,
                             cudaFuncAttributeMaxDynamicSharedMemorySize, ATTN_SMEM_BYTES);
        attr_set = true;
    }

    tf32_gemm_bias<<<dim3(2 * C_ / BN, M_ / BM), blk, GEMM_SMEM_BYTES>>>(x, Wqk, bqk, qk, M_, 2 * C_, C_);
    tf32_gemm_bias<<<dim3(VBD_ / BN, M_ / BM), blk, GEMM_SMEM_BYTES>>>(x, Wv, bv, v, M_, VBD_, C_);
    tf32_gemm_bias<<<dim3(VBD_ / BN, M_ / BM), blk, GEMM_SMEM_BYTES>>>(x, Wg, bg, g, M_, VBD_, C_);

    retention_attn_tc<<<dim3(T_ / 64, B_ * H_), blk, ATTN_SMEM_BYTES>>>(qk, v, g, y);

    tf32_gemm_bias<<<dim3(C_ / BN, M_ / BM), blk, GEMM_SMEM_BYTES>>>(y, Wo, bo, out, M_, C_, 2 * C_);
}